// round 15
// baseline (speedup 1.0000x reference)
#include <cuda_runtime.h>
#include <cuda_bf16.h>
#include <mma.h>
#include <math.h>
#include <cstdint>

using namespace nvcuda;

// ---------------- scratch (static device globals; no allocations) ----------
__device__ float g_bqkv[1536];
__device__ float g_bg1[256];
__device__ __nv_bfloat16 g_Wq_hi[786432];  // [1536,512]
__device__ __nv_bfloat16 g_Wq_lo[786432];
__device__ __nv_bfloat16 g_Wg_hi[131072];  // [256,512]
__device__ __nv_bfloat16 g_Wg_lo[131072];
__device__ __nv_bfloat16 g_Xhi[16777216];  // [8,512,4096]
__device__ __nv_bfloat16 g_Xlo[16777216];
__device__ float g_qkvp[50331648];
__device__ float g_qkv[50331648];
__device__ float g_g1[8388608];
__device__ float g_ss[12288];
__device__ float g_partial[128];
__device__ float g_qinv[4096];
__device__ float g_kinv[4096];
__device__ float g_Spart[2097152];   // [8 chunk][64 bh][64][64]
__device__ float g_P[262144];        // [64 bh][64][64]
__device__ int   g_dk;

// ---------------- cp.async helpers ------------------------------------------
__device__ __forceinline__ uint32_t cvta_sh(const void* p) {
    return (uint32_t)__cvta_generic_to_shared(p);
}
#define CP16(dst, src) \
    asm volatile("cp.async.cg.shared.global [%0], [%1], 16;" :: "r"(dst), "l"(src))
#define CP_COMMIT() asm volatile("cp.async.commit_group;" ::: "memory")
#define CP_WAIT1()  asm volatile("cp.async.wait_group 1;" ::: "memory")
#define CP_WAIT0()  asm volatile("cp.async.wait_group 0;" ::: "memory")

// ===== bf16x3 GEMM, cp.async 2-stage, CTA 128x128, 8 warps @ 32x64, 2 CTA/SM =
static constexpr int LDA = 40;
static constexpr int LDB = 136;                       // 128 + 8 pad
static constexpr uint32_t A_T = 128 * LDA;            // 5120 elems
static constexpr uint32_t B_T = 32 * LDB;             // 4352 elems
static constexpr uint32_t STG = 2 * A_T + 2 * B_T;    // 18944 elems
static constexpr uint32_t GEMM_SMEM = STG * 2 * 2;    // 75776 bytes

__global__ void __launch_bounds__(256, 2) mma_gemm(
    const __nv_bfloat16* __restrict__ Whi, const __nv_bfloat16* __restrict__ Wlo,
    const __nv_bfloat16* __restrict__ Xhi, const __nv_bfloat16* __restrict__ Xlo,
    float* __restrict__ C, int Mtotal, int batch_off)
{
    extern __shared__ __nv_bfloat16 sm[];

    const int tid = threadIdx.x;
    const int wid = tid >> 5;
    const int wm = wid >> 1;          // 0..3 -> rows wm*32
    const int wn = wid & 1;           // 0..1 -> cols wn*64

    const int bm = blockIdx.x << 7;
    const int n0 = blockIdx.y << 7;
    const int batch = batch_off + blockIdx.z;

    const __nv_bfloat16* Ahi = Whi + (size_t)bm * 512;
    const __nv_bfloat16* Alo = Wlo + (size_t)bm * 512;
    const __nv_bfloat16* Xb_hi = Xhi + (size_t)batch * 512 * 4096 + n0;
    const __nv_bfloat16* Xb_lo = Xlo + (size_t)batch * 512 * 4096 + n0;

    const int arow = tid >> 1, aq = (tid & 1) * 16;
    const int brow = tid >> 4, bq = (tid & 15) * 8;

    auto prefetch = [&](int c) {
        if (c < 16) {
            const int k0 = c << 5;
            __nv_bfloat16* st = sm + (size_t)(c & 1) * STG;
            CP16(cvta_sh(st + arow * LDA + aq), Ahi + (size_t)arow * 512 + k0 + aq);
            CP16(cvta_sh(st + arow * LDA + aq + 8), Ahi + (size_t)arow * 512 + k0 + aq + 8);
            CP16(cvta_sh(st + A_T + arow * LDA + aq), Alo + (size_t)arow * 512 + k0 + aq);
            CP16(cvta_sh(st + A_T + arow * LDA + aq + 8), Alo + (size_t)arow * 512 + k0 + aq + 8);
            #pragma unroll
            for (int p = 0; p < 2; p++) {
                int r = brow + p * 16;
                CP16(cvta_sh(st + 2 * A_T + r * LDB + bq),
                     Xb_hi + (size_t)(k0 + r) * 4096 + bq);
                CP16(cvta_sh(st + 2 * A_T + B_T + r * LDB + bq),
                     Xb_lo + (size_t)(k0 + r) * 4096 + bq);
            }
        }
        CP_COMMIT();
    };

    wmma::fragment<wmma::accumulator, 16, 16, 16, float> acc[2][4];
    #pragma unroll
    for (int i = 0; i < 2; i++)
        #pragma unroll
        for (int j = 0; j < 4; j++) wmma::fill_fragment(acc[i][j], 0.f);

    prefetch(0);
    prefetch(1);

    for (int c = 0; c < 16; c++) {
        CP_WAIT1();
        __syncthreads();

        const __nv_bfloat16* st = sm + (size_t)(c & 1) * STG;
        const __nv_bfloat16* A0 = st;
        const __nv_bfloat16* A1 = st + A_T;
        const __nv_bfloat16* B0 = st + 2 * A_T;
        const __nv_bfloat16* B1 = st + 2 * A_T + B_T;

        #pragma unroll
        for (int ks = 0; ks < 2; ks++) {
            wmma::fragment<wmma::matrix_b, 16, 16, 16, __nv_bfloat16, wmma::row_major> bh[4];
            wmma::fragment<wmma::matrix_a, 16, 16, 16, __nv_bfloat16, wmma::row_major> ah[2];
            #pragma unroll
            for (int ni = 0; ni < 4; ni++)
                wmma::load_matrix_sync(bh[ni],
                    &B0[(ks * 16) * LDB + wn * 64 + ni * 16], LDB);
            #pragma unroll
            for (int mi = 0; mi < 2; mi++)
                wmma::load_matrix_sync(ah[mi],
                    &A0[(wm * 32 + mi * 16) * LDA + ks * 16], LDA);
            #pragma unroll
            for (int mi = 0; mi < 2; mi++)
                #pragma unroll
                for (int ni = 0; ni < 4; ni++)
                    wmma::mma_sync(acc[mi][ni], ah[mi], bh[ni], acc[mi][ni]);
            {
                wmma::fragment<wmma::matrix_a, 16, 16, 16, __nv_bfloat16, wmma::row_major> al[2];
                #pragma unroll
                for (int mi = 0; mi < 2; mi++)
                    wmma::load_matrix_sync(al[mi],
                        &A1[(wm * 32 + mi * 16) * LDA + ks * 16], LDA);
                #pragma unroll
                for (int mi = 0; mi < 2; mi++)
                    #pragma unroll
                    for (int ni = 0; ni < 4; ni++)
                        wmma::mma_sync(acc[mi][ni], al[mi], bh[ni], acc[mi][ni]);
            }
            {
                wmma::fragment<wmma::matrix_b, 16, 16, 16, __nv_bfloat16, wmma::row_major> bl[4];
                #pragma unroll
                for (int ni = 0; ni < 4; ni++)
                    wmma::load_matrix_sync(bl[ni],
                        &B1[(ks * 16) * LDB + wn * 64 + ni * 16], LDB);
                #pragma unroll
                for (int mi = 0; mi < 2; mi++)
                    #pragma unroll
                    for (int ni = 0; ni < 4; ni++)
                        wmma::mma_sync(acc[mi][ni], ah[mi], bl[ni], acc[mi][ni]);
            }
        }
        __syncthreads();
        prefetch(c + 2);
    }
    CP_WAIT0();

    float* Cb = C + (size_t)batch * Mtotal * 4096;
    #pragma unroll
    for (int mi = 0; mi < 2; mi++)
        #pragma unroll
        for (int ni = 0; ni < 4; ni++)
            wmma::store_matrix_sync(
                Cb + (size_t)(bm + wm * 32 + mi * 16) * 4096 + n0 + wn * 64 + ni * 16,
                acc[mi][ni], 4096, wmma::mem_row_major);
}

// ---------------- vectorized split fp32 -> bf16 hi/lo ------------------------
__device__ __forceinline__ uint32_t pack2(float a, float b) {
    __nv_bfloat162 t = __floats2bfloat162_rn(a, b);
    return *reinterpret_cast<uint32_t*>(&t);
}
__global__ void split4_kernel(const float4* __restrict__ in,
                              uint2* __restrict__ hi, uint2* __restrict__ lo, int n4)
{
    int i = blockIdx.x * 256 + threadIdx.x;
    if (i < n4) {
        float4 v = in[i];
        float h0 = __bfloat162float(__float2bfloat16(v.x));
        float h1 = __bfloat162float(__float2bfloat16(v.y));
        float h2 = __bfloat162float(__float2bfloat16(v.z));
        float h3 = __bfloat162float(__float2bfloat16(v.w));
        hi[i] = make_uint2(pack2(h0, h1), pack2(h2, h3));
        lo[i] = make_uint2(pack2(v.x - h0, v.y - h1), pack2(v.z - h2, v.w - h3));
    }
}

// ------- fold GEMM, 64x64 tiles, bf16 hi/lo epilogue --------------------------
__global__ void __launch_bounds__(256) sgemm_fold64(
    const float* __restrict__ A, const float* __restrict__ Bm,
    __nv_bfloat16* __restrict__ Hi, __nv_bfloat16* __restrict__ Lo,
    int N, int K)
{
    __shared__ float As[32][68];
    __shared__ float Bs[32][68];
    const int bm = blockIdx.y * 64;
    const int bn = blockIdx.x * 64;
    const int tid = threadIdx.x;
    const int tx = tid & 15, ty = tid >> 4;

    const int ar = tid >> 2, ac = (tid & 3) * 8;
    const int br = tid >> 3, bc = (tid & 7) * 8;

    float acc[4][4] = {};
    for (int k0 = 0; k0 < K; k0 += 32) {
        float4 a0 = *reinterpret_cast<const float4*>(A + (size_t)(bm + ar) * K + k0 + ac);
        float4 a1 = *reinterpret_cast<const float4*>(A + (size_t)(bm + ar) * K + k0 + ac + 4);
        As[ac + 0][ar] = a0.x; As[ac + 1][ar] = a0.y;
        As[ac + 2][ar] = a0.z; As[ac + 3][ar] = a0.w;
        As[ac + 4][ar] = a1.x; As[ac + 5][ar] = a1.y;
        As[ac + 6][ar] = a1.z; As[ac + 7][ar] = a1.w;
        *reinterpret_cast<float4*>(&Bs[br][bc]) =
            *reinterpret_cast<const float4*>(Bm + (size_t)(k0 + br) * N + bn + bc);
        *reinterpret_cast<float4*>(&Bs[br][bc + 4]) =
            *reinterpret_cast<const float4*>(Bm + (size_t)(k0 + br) * N + bn + bc + 4);
        __syncthreads();
        #pragma unroll
        for (int kk = 0; kk < 32; kk++) {
            float ar4[4], br4[4];
            #pragma unroll
            for (int i = 0; i < 4; i++) ar4[i] = As[kk][ty * 4 + i];
            #pragma unroll
            for (int j = 0; j < 4; j++) br4[j] = Bs[kk][tx * 4 + j];
            #pragma unroll
            for (int i = 0; i < 4; i++)
                #pragma unroll
                for (int j = 0; j < 4; j++)
                    acc[i][j] = fmaf(ar4[i], br4[j], acc[i][j]);
        }
        __syncthreads();
    }
    #pragma unroll
    for (int i = 0; i < 4; i++) {
        int m = bm + ty * 4 + i;
        #pragma unroll
        for (int j = 0; j < 4; j++) {
            float v = acc[i][j];
            __nv_bfloat16 h = __float2bfloat16(v);
            Hi[(size_t)m * N + bn + tx * 4 + j] = h;
            Lo[(size_t)m * N + bn + tx * 4 + j] =
                __float2bfloat16(v - __bfloat162float(h));
        }
    }
}

// ---------------- fold biases: one warp per output row -----------------------
__global__ void __launch_bounds__(256) fold_bias(
    const float* __restrict__ wqkv, const float* __restrict__ wg1,
    const float* __restrict__ bg1, const float* __restrict__ b0)
{
    const int warp = (blockIdx.x * 256 + threadIdx.x) >> 5;
    const int lane = threadIdx.x & 31;
    if (warp >= 1792) return;
    const float* row = (warp < 1536) ? (wqkv + (size_t)warp * 512)
                                     : (wg1 + (size_t)(warp - 1536) * 512);
    float s = 0.f;
    #pragma unroll
    for (int k = 0; k < 16; k++)
        s = fmaf(row[lane + k * 32], b0[lane + k * 32], s);
    #pragma unroll
    for (int off = 16; off > 0; off >>= 1)
        s += __shfl_down_sync(0xffffffffu, s, off);
    if (lane == 0) {
        if (warp < 1536) g_bqkv[warp] = s;
        else             g_bg1[warp - 1536] = s + bg1[warp - 1536];
    }
}

// ------- depthwise 3x3 SAME, bias fused, sumsq fused -------------------------
__global__ void __launch_bounds__(256) dwconv_kernel(
    const float* __restrict__ inp, const float* __restrict__ w,
    const float* __restrict__ bias, float* __restrict__ outp, int bc0)
{
    const int bc = bc0 + blockIdx.x;
    const int ch = bc % 1536;
    const float* ip = inp + (size_t)bc * 4096;
    float*       op = outp + (size_t)bc * 4096;
    __shared__ float sh[66 * 66];
    __shared__ float red[256];
    const int tid = threadIdx.x;
    const float bv = bias[ch];
    for (int i = tid; i < 66 * 66; i += 256) {
        int r = i / 66 - 1;
        int c = i % 66 - 1;
        sh[i] = (r >= 0 && r < 64 && c >= 0 && c < 64) ? ip[r * 64 + c] + bv : 0.f;
    }
    const float* wp = w + (size_t)ch * 9;
    float w0 = wp[0], w1 = wp[1], w2 = wp[2];
    float w3 = wp[3], w4 = wp[4], w5 = wp[5];
    float w6 = wp[6], w7 = wp[7], w8 = wp[8];
    __syncthreads();
    float ss = 0.f;
    #pragma unroll
    for (int j = 0; j < 16; j++) {
        int p = tid + j * 256;
        int y = p >> 6, x = p & 63;
        const float* s0 = &sh[y * 66 + x];
        float o = s0[0]   * w0 + s0[1]   * w1 + s0[2]   * w2
                + s0[66]  * w3 + s0[67]  * w4 + s0[68]  * w5
                + s0[132] * w6 + s0[133] * w7 + s0[134] * w8;
        op[p] = o;
        ss = fmaf(o, o, ss);
    }
    red[tid] = ss;
    __syncthreads();
    for (int st = 128; st > 0; st >>= 1) {
        if (tid < st) red[tid] += red[tid + st];
        __syncthreads();
    }
    if (tid == 0) g_ss[bc] = red[0];
}

// ---------------- inverse norms (per batch pair) ------------------------------
__global__ void inv_norm_pair(int b0)
{
    int i = blockIdx.x * 256 + threadIdx.x;   // 0..2047
    if (i < 2048) {
        int b = b0 + (i >> 10);
        int r = i & 1023;
        int qk = r >> 9;
        int hc = r & 511;
        float ss = g_ss[b * 1536 + qk * 512 + hc];
        float inv = 1.f / fmaxf(sqrtf(ss), 1e-12f);
        (qk ? g_kinv : g_qinv)[b * 512 + hc] = inv;
    }
}

// ---------------- gate: bias+relu fused, sigmoid dot, partial sums ----------
__global__ void __launch_bounds__(256) gate_dot(
    const float* __restrict__ g1, const float* __restrict__ wg2,
    const float* __restrict__ bg1f, const float* __restrict__ bg2)
{
    __shared__ float ws[256];
    __shared__ float bs[256];
    __shared__ float red[256];
    const int tid = threadIdx.x;
    ws[tid] = wg2[tid];
    bs[tid] = bg1f[tid];
    __syncthreads();
    const int P = blockIdx.x * 256 + tid;
    const int b = P >> 12;
    const int p = P & 4095;
    const float* base = g1 + (size_t)b * 256 * 4096 + p;
    float acc = bg2[0];
    #pragma unroll 8
    for (int ch = 0; ch < 256; ch++)
        acc = fmaf(fmaxf(base[(size_t)ch * 4096] + bs[ch], 0.f), ws[ch], acc);
    float s = 1.f / (1.f + expf(-acc));
    red[tid] = s;
    __syncthreads();
    for (int st = 128; st > 0; st >>= 1) {
        if (tid < st) red[tid] += red[tid + st];
        __syncthreads();
    }
    if (tid == 0) g_partial[blockIdx.x] = red[0];
}

__global__ void gate_fin()
{
    if (threadIdx.x == 0 && blockIdx.x == 0) {
        float t = 0.f;
        for (int i = 0; i < 128; i++) t += g_partial[i];
        float mean = t * (1.f / 32768.f);
        int k = (int)floorf(64.f * mean);
        g_dk = max(0, min(64, k));
    }
}

// -------- split-K QK^T partials, register double-buffered ---------------------
__global__ void __launch_bounds__(256) qk_gemm(const float* __restrict__ qkv, int bh0)
{
    __shared__ float Qt[64 * 68];
    __shared__ float Kt[64 * 68];

    const int bh = bh0 + blockIdx.y;
    const int b = bh >> 3, h = bh & 7;
    const float* Qg = qkv + ((size_t)b * 1536 + (size_t)h * 64) * 4096;
    const float* Kg = Qg + (size_t)512 * 4096;
    const int n_base = blockIdx.x * 512;

    const int tid = threadIdx.x;
    const int tx = tid & 15, ty = tid >> 4;

    int rowl[4], nll[4];
    #pragma unroll
    for (int l = 0; l < 4; l++) {
        int f = tid + l * 256;
        rowl[l] = f >> 4;
        nll[l]  = (f & 15) * 4;
    }

    float4 rq[4], rk[4];
    auto loadg = [&](int n0) {
        #pragma unroll
        for (int l = 0; l < 4; l++) {
            rq[l] = *reinterpret_cast<const float4*>(Qg + (size_t)rowl[l] * 4096 + n0 + nll[l]);
            rk[l] = *reinterpret_cast<const float4*>(Kg + (size_t)rowl[l] * 4096 + n0 + nll[l]);
        }
    };
    auto stores = [&]() {
        #pragma unroll
        for (int l = 0; l < 4; l++) {
            Qt[(nll[l] + 0) * 68 + rowl[l]] = rq[l].x;
            Qt[(nll[l] + 1) * 68 + rowl[l]] = rq[l].y;
            Qt[(nll[l] + 2) * 68 + rowl[l]] = rq[l].z;
            Qt[(nll[l] + 3) * 68 + rowl[l]] = rq[l].w;
            Kt[(nll[l] + 0) * 68 + rowl[l]] = rk[l].x;
            Kt[(nll[l] + 1) * 68 + rowl[l]] = rk[l].y;
            Kt[(nll[l] + 2) * 68 + rowl[l]] = rk[l].z;
            Kt[(nll[l] + 3) * 68 + rowl[l]] = rk[l].w;
        }
    };

    loadg(n_base);
    stores();
    __syncthreads();

    float acc[4][4] = {};
    for (int t = 0; t < 8; t++) {
        const bool more = (t + 1) < 8;
        if (more) loadg(n_base + (t + 1) * 64);
        #pragma unroll 8
        for (int nn = 0; nn < 64; nn++) {
            float4 av = *reinterpret_cast<const float4*>(&Qt[nn * 68 + ty * 4]);
            float4 bv = *reinterpret_cast<const float4*>(&Kt[nn * 68 + tx * 4]);
            float ar[4] = {av.x, av.y, av.z, av.w};
            float br[4] = {bv.x, bv.y, bv.z, bv.w};
            #pragma unroll
            for (int i = 0; i < 4; i++)
                #pragma unroll
                for (int j = 0; j < 4; j++)
                    acc[i][j] = fmaf(ar[i], br[j], acc[i][j]);
        }
        if (more) {
            __syncthreads();
            stores();
            __syncthreads();
        }
    }
    float* Sp = &g_Spart[((size_t)blockIdx.x * 64 + bh) * 4096];
    #pragma unroll
    for (int i = 0; i < 4; i++) {
        float4 v;
        v.x = acc[i][0]; v.y = acc[i][1]; v.z = acc[i][2]; v.w = acc[i][3];
        *reinterpret_cast<float4*>(&Sp[(ty * 4 + i) * 64 + tx * 4]) = v;
    }
}

// ------- reduce + scale + warp-parallel top-k + softmax ----------------------
__global__ void __launch_bounds__(256) topk_softmax(const float* __restrict__ temp, int bh0)
{
    __shared__ float S[64 * 65];
    const int bh = bh0 + blockIdx.x;
    const int b = bh >> 3, h = bh & 7;
    const int tid = threadIdx.x;
    const int base = b * 512 + h * 64;
    const float tmp = temp[h];

    for (int e = tid; e < 4096; e += 256) {
        float s = 0.f;
        #pragma unroll
        for (int c = 0; c < 8; c++)
            s += g_Spart[((size_t)c * 64 + bh) * 4096 + e];
        int row = e >> 6, col = e & 63;
        S[row * 65 + col] = s * g_qinv[base + row] * tmp * g_kinv[base + col];
    }
    __syncthreads();

    const int kd = g_dk;
    const int warp = tid >> 5, lane = tid & 31;
    for (int r = warp; r < 64; r += 8) {
        float* row = &S[r * 65];
        float a0 = row[lane], a1 = row[lane + 32];
        int c0 = 0, c1 = 0;
        #pragma unroll 8
        for (int j = 0; j < 64; j++) {
            float aj = row[j];
            c0 += (aj > a0) || (aj == a0 && j < lane);
            c1 += (aj > a1) || (aj == a1 && j < lane + 32);
        }
        bool k0 = c0 < kd, k1 = c1 < kd;
        float m = fmaxf(k0 ? a0 : -INFINITY, k1 ? a1 : -INFINITY);
        #pragma unroll
        for (int off = 16; off > 0; off >>= 1)
            m = fmaxf(m, __shfl_xor_sync(0xffffffffu, m, off));
        float e0 = k0 ? expf(a0 - m) : 0.f;
        float e1 = k1 ? expf(a1 - m) : 0.f;
        float s = e0 + e1;
        #pragma unroll
        for (int off = 16; off > 0; off >>= 1)
            s += __shfl_xor_sync(0xffffffffu, s, off);
        float inv = (s > 0.f) ? 1.f / s : 0.f;
        row[lane] = e0 * inv;
        row[lane + 32] = e1 * inv;
    }
    __syncthreads();
    for (int e = tid; e < 4096; e += 256) {
        int row = e >> 6, col = e & 63;
        g_P[(size_t)bh * 4096 + e] = S[row * 65 + col];
    }
}

// ------- out = sc * P @ V, register double-buffered ---------------------------
__global__ void __launch_bounds__(256) av_gemm(
    const float* __restrict__ qkv,
    const float* __restrict__ a1p, const float* __restrict__ a2p,
    const float* __restrict__ a3p, const float* __restrict__ a4p,
    float* __restrict__ outp, int bh0)
{
    __shared__ float P[64 * 65];
    __shared__ float Vt[64 * 68];

    const int bh = bh0 + blockIdx.y;
    const int b = bh >> 3, h = bh & 7;
    const float* Vg = qkv + ((size_t)b * 1536 + 1024 + (size_t)h * 64) * 4096;
    float* Og = outp + ((size_t)b * 512 + (size_t)h * 64) * 4096;
    const int n_base = blockIdx.x * 512;
    const float sc = a1p[0] + a2p[0] + a3p[0] + a4p[0];

    const int tid = threadIdx.x;
    const int tx = tid & 15, ty = tid >> 4;

    int rowl[4], nll[4];
    #pragma unroll
    for (int l = 0; l < 4; l++) {
        int f = tid + l * 256;
        rowl[l] = f >> 4;
        nll[l]  = (f & 15) * 4;
    }
    float4 rv[4];
    auto loadg = [&](int n0) {
        #pragma unroll
        for (int l = 0; l < 4; l++)
            rv[l] = *reinterpret_cast<const float4*>(Vg + (size_t)rowl[l] * 4096 + n0 + nll[l]);
    };
    auto stores = [&]() {
        #pragma unroll
        for (int l = 0; l < 4; l++)
            *reinterpret_cast<float4*>(&Vt[rowl[l] * 68 + nll[l]]) = rv[l];
    };

    for (int e = tid; e < 4096; e += 256) {
        int row = e >> 6, col = e & 63;
        P[row * 65 + col] = g_P[(size_t)bh * 4096 + e];
    }
    loadg(n_base);
    __syncthreads();
    stores();
    __syncthreads();

    for (int t = 0; t < 8; t++) {
        const int n0 = n_base + t * 64;
        const bool more = (t + 1) < 8;
        if (more) loadg(n0 + 64);
        float o[4][4] = {};
        #pragma unroll 4
        for (int d = 0; d < 64; d++) {
            float s0 = P[(ty * 4 + 0) * 65 + d];
            float s1 = P[(ty * 4 + 1) * 65 + d];
            float s2 = P[(ty * 4 + 2) * 65 + d];
            float s3 = P[(ty * 4 + 3) * 65 + d];
            float4 v4 = *reinterpret_cast<const float4*>(&Vt[d * 68 + tx * 4]);
            o[0][0] = fmaf(s0, v4.x, o[0][0]); o[0][1] = fmaf(s0, v4.y, o[0][1]);
            o[0][2] = fmaf(s0, v4.z, o[0][2]); o[0][3] = fmaf(s0, v4.w, o[0][3]);
            o[1][0] = fmaf(s1, v4.x, o[1][0]); o[1][1] = fmaf(s1, v4.y, o[1][1]);
            o[1][2] = fmaf(s1, v4.z, o[1][2]); o[1][3] = fmaf(s1, v4.w, o[1][3]);
            o[2][0] = fmaf(s2, v4.x, o[2][0]); o[2][1] = fmaf(s2, v4.y, o[2][1]);
            o[2][2] = fmaf(s2, v4.z, o[2][2]); o[2][3] = fmaf(s2, v4.w, o[2][3]);
            o[3][0] = fmaf(s3, v4.x, o[3][0]); o[3][1] = fmaf(s3, v4.y, o[3][1]);
            o[3][2] = fmaf(s3, v4.z, o[3][2]); o[3][3] = fmaf(s3, v4.w, o[3][3]);
        }
        #pragma unroll
        for (int i = 0; i < 4; i++) {
            float4 w;
            w.x = o[i][0] * sc; w.y = o[i][1] * sc;
            w.z = o[i][2] * sc; w.w = o[i][3] * sc;
            *reinterpret_cast<float4*>(Og + (size_t)(ty * 4 + i) * 4096 + n0 + tx * 4) = w;
        }
        if (more) {
            __syncthreads();
            stores();
            __syncthreads();
        }
    }
}

// ---------------------------------------------------------------------------
extern "C" void kernel_launch(void* const* d_in, const int* in_sizes, int n_in,
                              void* d_out, int out_size)
{
    const float* x    = (const float*)d_in[0];
    const float* w0   = (const float*)d_in[1];
    const float* b0   = (const float*)d_in[2];
    const float* wqkv = (const float*)d_in[3];
    const float* wdw  = (const float*)d_in[4];
    const float* temp = (const float*)d_in[5];
    const float* wg1  = (const float*)d_in[6];
    const float* bg1  = (const float*)d_in[7];
    const float* wg2  = (const float*)d_in[8];
    const float* bg2  = (const float*)d_in[9];
    const float* a1   = (const float*)d_in[10];
    const float* a2   = (const float*)d_in[11];
    const float* a3   = (const float*)d_in[12];
    const float* a4   = (const float*)d_in[13];
    float* out = (float*)d_out;

    float *bqkv, *bg1f, *qkvp, *qkvb, *g1;
    __nv_bfloat16 *Wqh, *Wql, *Wgh, *Wgl, *Xh, *Xl;
    cudaGetSymbolAddress((void**)&bqkv, g_bqkv);
    cudaGetSymbolAddress((void**)&bg1f, g_bg1);
    cudaGetSymbolAddress((void**)&qkvp, g_qkvp);
    cudaGetSymbolAddress((void**)&qkvb, g_qkv);
    cudaGetSymbolAddress((void**)&g1,   g_g1);
    cudaGetSymbolAddress((void**)&Wqh,  g_Wq_hi);
    cudaGetSymbolAddress((void**)&Wql,  g_Wq_lo);
    cudaGetSymbolAddress((void**)&Wgh,  g_Wg_hi);
    cudaGetSymbolAddress((void**)&Wgl,  g_Wg_lo);
    cudaGetSymbolAddress((void**)&Xh,   g_Xhi);
    cudaGetSymbolAddress((void**)&Xl,   g_Xlo);

    cudaFuncSetAttribute(mma_gemm, cudaFuncAttributeMaxDynamicSharedMemorySize, GEMM_SMEM);

    static cudaStream_t s1 = nullptr, s2 = nullptr;
    static cudaEvent_t evRoot, evSPLIT, evW, evBIAS, evFIN;
    static cudaEvent_t evC[4], evQ[4];
    if (s1 == nullptr) {
        cudaStreamCreateWithFlags(&s1, cudaStreamNonBlocking);
        cudaStreamCreateWithFlags(&s2, cudaStreamNonBlocking);
        cudaEventCreateWithFlags(&evRoot,  cudaEventDisableTiming);
        cudaEventCreateWithFlags(&evSPLIT, cudaEventDisableTiming);
        cudaEventCreateWithFlags(&evW,     cudaEventDisableTiming);
        cudaEventCreateWithFlags(&evBIAS,  cudaEventDisableTiming);
        cudaEventCreateWithFlags(&evFIN,   cudaEventDisableTiming);
        for (int i = 0; i < 4; i++) {
            cudaEventCreateWithFlags(&evC[i], cudaEventDisableTiming);
            cudaEventCreateWithFlags(&evQ[i], cudaEventDisableTiming);
        }
    }

    dim3 blk(256);

    cudaEventRecord(evRoot, 0);
    cudaStreamWaitEvent(s1, evRoot, 0);
    cudaStreamWaitEvent(s2, evRoot, 0);

    // s0: x split
    split4_kernel<<<16384, blk>>>((const float4*)x, (uint2*)Xh, (uint2*)Xl, 4194304);
    cudaEventRecord(evSPLIT, 0);

    // s1: qkv weight fold
    sgemm_fold64<<<dim3(8, 24), blk, 0, s1>>>(wqkv, w0, Wqh, Wql, 512, 512);
    cudaEventRecord(evW, s1);

    // s2: gate weight fold + bias folds, then the gate pipeline
    sgemm_fold64<<<dim3(8, 4), blk, 0, s2>>>(wg1, w0, Wgh, Wgl, 512, 512);
    fold_bias<<<224, blk, 0, s2>>>(wqkv, wg1, bg1, b0);
    cudaEventRecord(evBIAS, s2);
    cudaStreamWaitEvent(s2, evSPLIT, 0);
    mma_gemm<<<dim3(2, 32, 8), blk, GEMM_SMEM, s2>>>(Wgh, Wgl, Xh, Xl, g1, 256, 0);
    gate_dot<<<128, blk, 0, s2>>>(g1, wg2, bg1f, bg2);
    gate_fin<<<1, 32, 0, s2>>>();

    // s0: qkv GEMM in 4 batch-pair chunks (128x128 CTAs, 2 CTAs/SM)
    cudaStreamWaitEvent(0, evW, 0);
    for (int p = 0; p < 4; p++) {
        mma_gemm<<<dim3(12, 32, 2), blk, GEMM_SMEM>>>(
            Wqh, Wql, Xh, Xl, qkvp, 1536, p * 2);
        cudaEventRecord(evC[p], 0);
    }

    // s1: pipelined dwconv + inv_norm + qk per batch pair
    cudaStreamWaitEvent(s1, evBIAS, 0);
    for (int p = 0; p < 4; p++) {
        cudaStreamWaitEvent(s1, evC[p], 0);
        dwconv_kernel<<<3072, blk, 0, s1>>>(qkvp, wdw, bqkv, qkvb, p * 3072);
        inv_norm_pair<<<8, blk, 0, s1>>>(p * 2);
        qk_gemm<<<dim3(8, 16), blk, 0, s1>>>(qkvb, p * 16);
        cudaEventRecord(evQ[p], s1);
    }

    // s2: per-pair topk + av (g_dk ready via stream order after gate_fin)
    for (int p = 0; p < 4; p++) {
        cudaStreamWaitEvent(s2, evQ[p], 0);
        topk_softmax<<<16, blk, 0, s2>>>(temp, p * 16);
        av_gemm<<<dim3(8, 16), blk, 0, s2>>>(qkvb, a1, a2, a3, a4, out, p * 16);
    }
    cudaEventRecord(evFIN, s2);

    // join back to the capture stream
    cudaStreamWaitEvent(0, evFIN, 0);
}

// round 16
// speedup vs baseline: 1.0315x; 1.0315x over previous
#include <cuda_runtime.h>
#include <cuda_bf16.h>
#include <mma.h>
#include <math.h>
#include <cstdint>

using namespace nvcuda;

// ---------------- scratch (static device globals; no allocations) ----------
__device__ float g_bqkv[1536];
__device__ float g_bg1[256];
__device__ __nv_bfloat16 g_Wq_hi[786432];  // [1536,512]
__device__ __nv_bfloat16 g_Wq_lo[786432];
__device__ __nv_bfloat16 g_Wg_hi[131072];  // [256,512]
__device__ __nv_bfloat16 g_Wg_lo[131072];
__device__ __nv_bfloat16 g_Xhi[16777216];  // [8,512,4096]
__device__ __nv_bfloat16 g_Xlo[16777216];
__device__ float g_qkvp[50331648];
__device__ float g_qkv[50331648];
__device__ float g_g1[8388608];
__device__ float g_ss[12288];
__device__ float g_partial[128];
__device__ float g_qinv[4096];
__device__ float g_kinv[4096];
__device__ float g_Spart[2097152];   // [8 chunk][64 bh][64][64]
__device__ int   g_dk;

// ---------------- cp.async helpers ------------------------------------------
__device__ __forceinline__ uint32_t cvta_sh(const void* p) {
    return (uint32_t)__cvta_generic_to_shared(p);
}
#define CP16(dst, src) \
    asm volatile("cp.async.cg.shared.global [%0], [%1], 16;" :: "r"(dst), "l"(src))
#define CP_COMMIT() asm volatile("cp.async.commit_group;" ::: "memory")
#define CP_WAIT1()  asm volatile("cp.async.wait_group 1;" ::: "memory")
#define CP_WAIT0()  asm volatile("cp.async.wait_group 0;" ::: "memory")

// ===== bf16x3 GEMM, cp.async 2-stage, CTA 128x128, 8 warps @ 32x64, 2 CTA/SM =
static constexpr int LDA = 40;
static constexpr int LDB = 136;                       // 128 + 8 pad
static constexpr uint32_t A_T = 128 * LDA;            // 5120 elems
static constexpr uint32_t B_T = 32 * LDB;             // 4352 elems
static constexpr uint32_t STG = 2 * A_T + 2 * B_T;    // 18944 elems
static constexpr uint32_t GEMM_SMEM = STG * 2 * 2;    // 75776 bytes

__global__ void __launch_bounds__(256, 2) mma_gemm(
    const __nv_bfloat16* __restrict__ Whi, const __nv_bfloat16* __restrict__ Wlo,
    const __nv_bfloat16* __restrict__ Xhi, const __nv_bfloat16* __restrict__ Xlo,
    float* __restrict__ C, int Mtotal, int batch_off)
{
    extern __shared__ __nv_bfloat16 sm[];

    const int tid = threadIdx.x;
    const int wid = tid >> 5;
    const int wm = wid >> 1;          // 0..3 -> rows wm*32
    const int wn = wid & 1;           // 0..1 -> cols wn*64

    const int bm = blockIdx.x << 7;
    const int n0 = blockIdx.y << 7;
    const int batch = batch_off + blockIdx.z;

    const __nv_bfloat16* Ahi = Whi + (size_t)bm * 512;
    const __nv_bfloat16* Alo = Wlo + (size_t)bm * 512;
    const __nv_bfloat16* Xb_hi = Xhi + (size_t)batch * 512 * 4096 + n0;
    const __nv_bfloat16* Xb_lo = Xlo + (size_t)batch * 512 * 4096 + n0;

    const int arow = tid >> 1, aq = (tid & 1) * 16;
    const int brow = tid >> 4, bq = (tid & 15) * 8;

    auto prefetch = [&](int c) {
        if (c < 16) {
            const int k0 = c << 5;
            __nv_bfloat16* st = sm + (size_t)(c & 1) * STG;
            CP16(cvta_sh(st + arow * LDA + aq), Ahi + (size_t)arow * 512 + k0 + aq);
            CP16(cvta_sh(st + arow * LDA + aq + 8), Ahi + (size_t)arow * 512 + k0 + aq + 8);
            CP16(cvta_sh(st + A_T + arow * LDA + aq), Alo + (size_t)arow * 512 + k0 + aq);
            CP16(cvta_sh(st + A_T + arow * LDA + aq + 8), Alo + (size_t)arow * 512 + k0 + aq + 8);
            #pragma unroll
            for (int p = 0; p < 2; p++) {
                int r = brow + p * 16;
                CP16(cvta_sh(st + 2 * A_T + r * LDB + bq),
                     Xb_hi + (size_t)(k0 + r) * 4096 + bq);
                CP16(cvta_sh(st + 2 * A_T + B_T + r * LDB + bq),
                     Xb_lo + (size_t)(k0 + r) * 4096 + bq);
            }
        }
        CP_COMMIT();
    };

    wmma::fragment<wmma::accumulator, 16, 16, 16, float> acc[2][4];
    #pragma unroll
    for (int i = 0; i < 2; i++)
        #pragma unroll
        for (int j = 0; j < 4; j++) wmma::fill_fragment(acc[i][j], 0.f);

    prefetch(0);
    prefetch(1);

    for (int c = 0; c < 16; c++) {
        CP_WAIT1();
        __syncthreads();

        const __nv_bfloat16* st = sm + (size_t)(c & 1) * STG;
        const __nv_bfloat16* A0 = st;
        const __nv_bfloat16* A1 = st + A_T;
        const __nv_bfloat16* B0 = st + 2 * A_T;
        const __nv_bfloat16* B1 = st + 2 * A_T + B_T;

        #pragma unroll
        for (int ks = 0; ks < 2; ks++) {
            wmma::fragment<wmma::matrix_b, 16, 16, 16, __nv_bfloat16, wmma::row_major> bh[4];
            wmma::fragment<wmma::matrix_a, 16, 16, 16, __nv_bfloat16, wmma::row_major> ah[2];
            #pragma unroll
            for (int ni = 0; ni < 4; ni++)
                wmma::load_matrix_sync(bh[ni],
                    &B0[(ks * 16) * LDB + wn * 64 + ni * 16], LDB);
            #pragma unroll
            for (int mi = 0; mi < 2; mi++)
                wmma::load_matrix_sync(ah[mi],
                    &A0[(wm * 32 + mi * 16) * LDA + ks * 16], LDA);
            #pragma unroll
            for (int mi = 0; mi < 2; mi++)
                #pragma unroll
                for (int ni = 0; ni < 4; ni++)
                    wmma::mma_sync(acc[mi][ni], ah[mi], bh[ni], acc[mi][ni]);
            {
                wmma::fragment<wmma::matrix_a, 16, 16, 16, __nv_bfloat16, wmma::row_major> al[2];
                #pragma unroll
                for (int mi = 0; mi < 2; mi++)
                    wmma::load_matrix_sync(al[mi],
                        &A1[(wm * 32 + mi * 16) * LDA + ks * 16], LDA);
                #pragma unroll
                for (int mi = 0; mi < 2; mi++)
                    #pragma unroll
                    for (int ni = 0; ni < 4; ni++)
                        wmma::mma_sync(acc[mi][ni], al[mi], bh[ni], acc[mi][ni]);
            }
            {
                wmma::fragment<wmma::matrix_b, 16, 16, 16, __nv_bfloat16, wmma::row_major> bl[4];
                #pragma unroll
                for (int ni = 0; ni < 4; ni++)
                    wmma::load_matrix_sync(bl[ni],
                        &B1[(ks * 16) * LDB + wn * 64 + ni * 16], LDB);
                #pragma unroll
                for (int mi = 0; mi < 2; mi++)
                    #pragma unroll
                    for (int ni = 0; ni < 4; ni++)
                        wmma::mma_sync(acc[mi][ni], ah[mi], bl[ni], acc[mi][ni]);
            }
        }
        __syncthreads();
        prefetch(c + 2);
    }
    CP_WAIT0();

    float* Cb = C + (size_t)batch * Mtotal * 4096;
    #pragma unroll
    for (int mi = 0; mi < 2; mi++)
        #pragma unroll
        for (int ni = 0; ni < 4; ni++)
            wmma::store_matrix_sync(
                Cb + (size_t)(bm + wm * 32 + mi * 16) * 4096 + n0 + wn * 64 + ni * 16,
                acc[mi][ni], 4096, wmma::mem_row_major);
}

// ---------------- vectorized split fp32 -> bf16 hi/lo ------------------------
__device__ __forceinline__ uint32_t pack2(float a, float b) {
    __nv_bfloat162 t = __floats2bfloat162_rn(a, b);
    return *reinterpret_cast<uint32_t*>(&t);
}
__global__ void split4_kernel(const float4* __restrict__ in,
                              uint2* __restrict__ hi, uint2* __restrict__ lo, int n4)
{
    int i = blockIdx.x * 256 + threadIdx.x;
    if (i < n4) {
        float4 v = in[i];
        float h0 = __bfloat162float(__float2bfloat16(v.x));
        float h1 = __bfloat162float(__float2bfloat16(v.y));
        float h2 = __bfloat162float(__float2bfloat16(v.z));
        float h3 = __bfloat162float(__float2bfloat16(v.w));
        hi[i] = make_uint2(pack2(h0, h1), pack2(h2, h3));
        lo[i] = make_uint2(pack2(v.x - h0, v.y - h1), pack2(v.z - h2, v.w - h3));
    }
}

// ------- fold GEMM, 64x64 tiles, bf16 hi/lo epilogue --------------------------
__global__ void __launch_bounds__(256) sgemm_fold64(
    const float* __restrict__ A, const float* __restrict__ Bm,
    __nv_bfloat16* __restrict__ Hi, __nv_bfloat16* __restrict__ Lo,
    int N, int K)
{
    __shared__ float As[32][68];
    __shared__ float Bs[32][68];
    const int bm = blockIdx.y * 64;
    const int bn = blockIdx.x * 64;
    const int tid = threadIdx.x;
    const int tx = tid & 15, ty = tid >> 4;

    const int ar = tid >> 2, ac = (tid & 3) * 8;
    const int br = tid >> 3, bc = (tid & 7) * 8;

    float acc[4][4] = {};
    for (int k0 = 0; k0 < K; k0 += 32) {
        float4 a0 = *reinterpret_cast<const float4*>(A + (size_t)(bm + ar) * K + k0 + ac);
        float4 a1 = *reinterpret_cast<const float4*>(A + (size_t)(bm + ar) * K + k0 + ac + 4);
        As[ac + 0][ar] = a0.x; As[ac + 1][ar] = a0.y;
        As[ac + 2][ar] = a0.z; As[ac + 3][ar] = a0.w;
        As[ac + 4][ar] = a1.x; As[ac + 5][ar] = a1.y;
        As[ac + 6][ar] = a1.z; As[ac + 7][ar] = a1.w;
        *reinterpret_cast<float4*>(&Bs[br][bc]) =
            *reinterpret_cast<const float4*>(Bm + (size_t)(k0 + br) * N + bn + bc);
        *reinterpret_cast<float4*>(&Bs[br][bc + 4]) =
            *reinterpret_cast<const float4*>(Bm + (size_t)(k0 + br) * N + bn + bc + 4);
        __syncthreads();
        #pragma unroll
        for (int kk = 0; kk < 32; kk++) {
            float ar4[4], br4[4];
            #pragma unroll
            for (int i = 0; i < 4; i++) ar4[i] = As[kk][ty * 4 + i];
            #pragma unroll
            for (int j = 0; j < 4; j++) br4[j] = Bs[kk][tx * 4 + j];
            #pragma unroll
            for (int i = 0; i < 4; i++)
                #pragma unroll
                for (int j = 0; j < 4; j++)
                    acc[i][j] = fmaf(ar4[i], br4[j], acc[i][j]);
        }
        __syncthreads();
    }
    #pragma unroll
    for (int i = 0; i < 4; i++) {
        int m = bm + ty * 4 + i;
        #pragma unroll
        for (int j = 0; j < 4; j++) {
            float v = acc[i][j];
            __nv_bfloat16 h = __float2bfloat16(v);
            Hi[(size_t)m * N + bn + tx * 4 + j] = h;
            Lo[(size_t)m * N + bn + tx * 4 + j] =
                __float2bfloat16(v - __bfloat162float(h));
        }
    }
}

// ---------------- fold biases: one warp per output row -----------------------
__global__ void __launch_bounds__(256) fold_bias(
    const float* __restrict__ wqkv, const float* __restrict__ wg1,
    const float* __restrict__ bg1, const float* __restrict__ b0)
{
    const int warp = (blockIdx.x * 256 + threadIdx.x) >> 5;
    const int lane = threadIdx.x & 31;
    if (warp >= 1792) return;
    const float* row = (warp < 1536) ? (wqkv + (size_t)warp * 512)
                                     : (wg1 + (size_t)(warp - 1536) * 512);
    float s = 0.f;
    #pragma unroll
    for (int k = 0; k < 16; k++)
        s = fmaf(row[lane + k * 32], b0[lane + k * 32], s);
    #pragma unroll
    for (int off = 16; off > 0; off >>= 1)
        s += __shfl_down_sync(0xffffffffu, s, off);
    if (lane == 0) {
        if (warp < 1536) g_bqkv[warp] = s;
        else             g_bg1[warp - 1536] = s + bg1[warp - 1536];
    }
}

// ------- depthwise 3x3 SAME, bias fused, sumsq fused -------------------------
__global__ void __launch_bounds__(256) dwconv_kernel(
    const float* __restrict__ inp, const float* __restrict__ w,
    const float* __restrict__ bias, float* __restrict__ outp, int bc0)
{
    const int bc = bc0 + blockIdx.x;
    const int ch = bc % 1536;
    const float* ip = inp + (size_t)bc * 4096;
    float*       op = outp + (size_t)bc * 4096;
    __shared__ float sh[66 * 66];
    __shared__ float red[256];
    const int tid = threadIdx.x;
    const float bv = bias[ch];
    for (int i = tid; i < 66 * 66; i += 256) {
        int r = i / 66 - 1;
        int c = i % 66 - 1;
        sh[i] = (r >= 0 && r < 64 && c >= 0 && c < 64) ? ip[r * 64 + c] + bv : 0.f;
    }
    const float* wp = w + (size_t)ch * 9;
    float w0 = wp[0], w1 = wp[1], w2 = wp[2];
    float w3 = wp[3], w4 = wp[4], w5 = wp[5];
    float w6 = wp[6], w7 = wp[7], w8 = wp[8];
    __syncthreads();
    float ss = 0.f;
    #pragma unroll
    for (int j = 0; j < 16; j++) {
        int p = tid + j * 256;
        int y = p >> 6, x = p & 63;
        const float* s0 = &sh[y * 66 + x];
        float o = s0[0]   * w0 + s0[1]   * w1 + s0[2]   * w2
                + s0[66]  * w3 + s0[67]  * w4 + s0[68]  * w5
                + s0[132] * w6 + s0[133] * w7 + s0[134] * w8;
        op[p] = o;
        ss = fmaf(o, o, ss);
    }
    red[tid] = ss;
    __syncthreads();
    for (int st = 128; st > 0; st >>= 1) {
        if (tid < st) red[tid] += red[tid + st];
        __syncthreads();
    }
    if (tid == 0) g_ss[bc] = red[0];
}

// ---------------- inverse norms ----------------------------------------------
__global__ void inv_norm()
{
    int i = blockIdx.x * 256 + threadIdx.x;
    if (i < 8192) {
        int qk = i >> 12;
        int rr = i & 4095;
        int b = rr >> 9, hc = rr & 511;
        float ss = g_ss[b * 1536 + qk * 512 + hc];
        float inv = 1.f / fmaxf(sqrtf(ss), 1e-12f);
        (qk ? g_kinv : g_qinv)[rr] = inv;
    }
}

// ---------------- gate: bias+relu fused, sigmoid dot, partial sums ----------
__global__ void __launch_bounds__(256) gate_dot(
    const float* __restrict__ g1, const float* __restrict__ wg2,
    const float* __restrict__ bg1f, const float* __restrict__ bg2)
{
    __shared__ float ws[256];
    __shared__ float bs[256];
    __shared__ float red[256];
    const int tid = threadIdx.x;
    ws[tid] = wg2[tid];
    bs[tid] = bg1f[tid];
    __syncthreads();
    const int P = blockIdx.x * 256 + tid;
    const int b = P >> 12;
    const int p = P & 4095;
    const float* base = g1 + (size_t)b * 256 * 4096 + p;
    float acc = bg2[0];
    #pragma unroll 8
    for (int ch = 0; ch < 256; ch++)
        acc = fmaf(fmaxf(base[(size_t)ch * 4096] + bs[ch], 0.f), ws[ch], acc);
    float s = 1.f / (1.f + expf(-acc));
    red[tid] = s;
    __syncthreads();
    for (int st = 128; st > 0; st >>= 1) {
        if (tid < st) red[tid] += red[tid + st];
        __syncthreads();
    }
    if (tid == 0) g_partial[blockIdx.x] = red[0];
}

__global__ void gate_fin()
{
    if (threadIdx.x == 0 && blockIdx.x == 0) {
        float t = 0.f;
        for (int i = 0; i < 128; i++) t += g_partial[i];
        float mean = t * (1.f / 32768.f);
        int k = (int)floorf(64.f * mean);
        g_dk = max(0, min(64, k));
    }
}

// -------- split-K QK^T partials, register double-buffered ---------------------
__global__ void __launch_bounds__(256) qk_gemm(const float* __restrict__ qkv, int bh0)
{
    __shared__ float Qt[64 * 68];
    __shared__ float Kt[64 * 68];

    const int bh = bh0 + blockIdx.y;
    const int b = bh >> 3, h = bh & 7;
    const float* Qg = qkv + ((size_t)b * 1536 + (size_t)h * 64) * 4096;
    const float* Kg = Qg + (size_t)512 * 4096;
    const int n_base = blockIdx.x * 512;

    const int tid = threadIdx.x;
    const int tx = tid & 15, ty = tid >> 4;

    int rowl[4], nll[4];
    #pragma unroll
    for (int l = 0; l < 4; l++) {
        int f = tid + l * 256;
        rowl[l] = f >> 4;
        nll[l]  = (f & 15) * 4;
    }

    float4 rq[4], rk[4];
    auto loadg = [&](int n0) {
        #pragma unroll
        for (int l = 0; l < 4; l++) {
            rq[l] = *reinterpret_cast<const float4*>(Qg + (size_t)rowl[l] * 4096 + n0 + nll[l]);
            rk[l] = *reinterpret_cast<const float4*>(Kg + (size_t)rowl[l] * 4096 + n0 + nll[l]);
        }
    };
    auto stores = [&]() {
        #pragma unroll
        for (int l = 0; l < 4; l++) {
            Qt[(nll[l] + 0) * 68 + rowl[l]] = rq[l].x;
            Qt[(nll[l] + 1) * 68 + rowl[l]] = rq[l].y;
            Qt[(nll[l] + 2) * 68 + rowl[l]] = rq[l].z;
            Qt[(nll[l] + 3) * 68 + rowl[l]] = rq[l].w;
            Kt[(nll[l] + 0) * 68 + rowl[l]] = rk[l].x;
            Kt[(nll[l] + 1) * 68 + rowl[l]] = rk[l].y;
            Kt[(nll[l] + 2) * 68 + rowl[l]] = rk[l].z;
            Kt[(nll[l] + 3) * 68 + rowl[l]] = rk[l].w;
        }
    };

    loadg(n_base);
    stores();
    __syncthreads();

    float acc[4][4] = {};
    for (int t = 0; t < 8; t++) {
        const bool more = (t + 1) < 8;
        if (more) loadg(n_base + (t + 1) * 64);
        #pragma unroll 8
        for (int nn = 0; nn < 64; nn++) {
            float4 av = *reinterpret_cast<const float4*>(&Qt[nn * 68 + ty * 4]);
            float4 bv = *reinterpret_cast<const float4*>(&Kt[nn * 68 + tx * 4]);
            float ar[4] = {av.x, av.y, av.z, av.w};
            float br[4] = {bv.x, bv.y, bv.z, bv.w};
            #pragma unroll
            for (int i = 0; i < 4; i++)
                #pragma unroll
                for (int j = 0; j < 4; j++)
                    acc[i][j] = fmaf(ar[i], br[j], acc[i][j]);
        }
        if (more) {
            __syncthreads();
            stores();
            __syncthreads();
        }
    }
    float* Sp = &g_Spart[((size_t)blockIdx.x * 64 + bh) * 4096];
    #pragma unroll
    for (int i = 0; i < 4; i++) {
        float4 v;
        v.x = acc[i][0]; v.y = acc[i][1]; v.z = acc[i][2]; v.w = acc[i][3];
        *reinterpret_cast<float4*>(&Sp[(ty * 4 + i) * 64 + tx * 4]) = v;
    }
}

// ===== fused: reduce partials + scale + top-k + softmax + P@V epilogue =======
// grid (8 n-chunks, 64 bh); each block rebuilds P for its bh (cheap, L2-hot)
// then computes out[:, n_chunk] = sc * P @ V.
__global__ void __launch_bounds__(256) attn_out(
    const float* __restrict__ qkv, const float* __restrict__ temp,
    const float* __restrict__ a1p, const float* __restrict__ a2p,
    const float* __restrict__ a3p, const float* __restrict__ a4p,
    float* __restrict__ outp)
{
    __shared__ float P[64 * 65];
    __shared__ float Vt[64 * 68];

    const int bh = blockIdx.y;
    const int b = bh >> 3, h = bh & 7;
    const float* Vg = qkv + ((size_t)b * 1536 + 1024 + (size_t)h * 64) * 4096;
    float* Og = outp + ((size_t)b * 512 + (size_t)h * 64) * 4096;
    const int n_base = blockIdx.x * 512;
    const float sc = a1p[0] + a2p[0] + a3p[0] + a4p[0];
    const int base = b * 512 + h * 64;
    const float tmp = temp[h];

    const int tid = threadIdx.x;
    const int tx = tid & 15, ty = tid >> 4;

    // V prefetch coords
    int rowl[4], nll[4];
    #pragma unroll
    for (int l = 0; l < 4; l++) {
        int f = tid + l * 256;
        rowl[l] = f >> 4;
        nll[l]  = (f & 15) * 4;
    }
    float4 rv[4];
    auto loadg = [&](int n0) {
        #pragma unroll
        for (int l = 0; l < 4; l++)
            rv[l] = *reinterpret_cast<const float4*>(Vg + (size_t)rowl[l] * 4096 + n0 + nll[l]);
    };
    auto storesV = [&]() {
        #pragma unroll
        for (int l = 0; l < 4; l++)
            *reinterpret_cast<float4*>(&Vt[rowl[l] * 68 + nll[l]]) = rv[l];
    };

    // build S: reduce 8 split-K partials + scale (V loads issued first to overlap)
    loadg(n_base);
    for (int e = tid; e < 4096; e += 256) {
        float s = 0.f;
        #pragma unroll
        for (int c = 0; c < 8; c++)
            s += g_Spart[((size_t)c * 64 + bh) * 4096 + e];
        int row = e >> 6, col = e & 63;
        P[row * 65 + col] = s * g_qinv[base + row] * tmp * g_kinv[base + col];
    }
    __syncthreads();

    // warp-parallel top-k + softmax (rows strided over 8 warps)
    const int kd = g_dk;
    const int warp = tid >> 5, lane = tid & 31;
    for (int r = warp; r < 64; r += 8) {
        float* row = &P[r * 65];
        float a0 = row[lane], a1 = row[lane + 32];
        int c0 = 0, c1 = 0;
        #pragma unroll 8
        for (int j = 0; j < 64; j++) {
            float aj = row[j];
            c0 += (aj > a0) || (aj == a0 && j < lane);
            c1 += (aj > a1) || (aj == a1 && j < lane + 32);
        }
        bool k0 = c0 < kd, k1 = c1 < kd;
        float m = fmaxf(k0 ? a0 : -INFINITY, k1 ? a1 : -INFINITY);
        #pragma unroll
        for (int off = 16; off > 0; off >>= 1)
            m = fmaxf(m, __shfl_xor_sync(0xffffffffu, m, off));
        float e0 = k0 ? expf(a0 - m) : 0.f;
        float e1 = k1 ? expf(a1 - m) : 0.f;
        float s = e0 + e1;
        #pragma unroll
        for (int off = 16; off > 0; off >>= 1)
            s += __shfl_xor_sync(0xffffffffu, s, off);
        float inv = (s > 0.f) ? 1.f / s : 0.f;
        row[lane] = e0 * inv;
        row[lane + 32] = e1 * inv;
    }
    __syncthreads();
    storesV();
    __syncthreads();

    // P @ V over this 512-wide n-chunk, register double-buffered V
    for (int t = 0; t < 8; t++) {
        const int n0 = n_base + t * 64;
        const bool more = (t + 1) < 8;
        if (more) loadg(n0 + 64);
        float o[4][4] = {};
        #pragma unroll 4
        for (int d = 0; d < 64; d++) {
            float s0 = P[(ty * 4 + 0) * 65 + d];
            float s1 = P[(ty * 4 + 1) * 65 + d];
            float s2 = P[(ty * 4 + 2) * 65 + d];
            float s3 = P[(ty * 4 + 3) * 65 + d];
            float4 v4 = *reinterpret_cast<const float4*>(&Vt[d * 68 + tx * 4]);
            o[0][0] = fmaf(s0, v4.x, o[0][0]); o[0][1] = fmaf(s0, v4.y, o[0][1]);
            o[0][2] = fmaf(s0, v4.z, o[0][2]); o[0][3] = fmaf(s0, v4.w, o[0][3]);
            o[1][0] = fmaf(s1, v4.x, o[1][0]); o[1][1] = fmaf(s1, v4.y, o[1][1]);
            o[1][2] = fmaf(s1, v4.z, o[1][2]); o[1][3] = fmaf(s1, v4.w, o[1][3]);
            o[2][0] = fmaf(s2, v4.x, o[2][0]); o[2][1] = fmaf(s2, v4.y, o[2][1]);
            o[2][2] = fmaf(s2, v4.z, o[2][2]); o[2][3] = fmaf(s2, v4.w, o[2][3]);
            o[3][0] = fmaf(s3, v4.x, o[3][0]); o[3][1] = fmaf(s3, v4.y, o[3][1]);
            o[3][2] = fmaf(s3, v4.z, o[3][2]); o[3][3] = fmaf(s3, v4.w, o[3][3]);
        }
        #pragma unroll
        for (int i = 0; i < 4; i++) {
            float4 w;
            w.x = o[i][0] * sc; w.y = o[i][1] * sc;
            w.z = o[i][2] * sc; w.w = o[i][3] * sc;
            *reinterpret_cast<float4*>(Og + (size_t)(ty * 4 + i) * 4096 + n0 + tx * 4) = w;
        }
        if (more) {
            __syncthreads();
            storesV();
            __syncthreads();
        }
    }
}

// ---------------------------------------------------------------------------
extern "C" void kernel_launch(void* const* d_in, const int* in_sizes, int n_in,
                              void* d_out, int out_size)
{
    const float* x    = (const float*)d_in[0];
    const float* w0   = (const float*)d_in[1];
    const float* b0   = (const float*)d_in[2];
    const float* wqkv = (const float*)d_in[3];
    const float* wdw  = (const float*)d_in[4];
    const float* temp = (const float*)d_in[5];
    const float* wg1  = (const float*)d_in[6];
    const float* bg1  = (const float*)d_in[7];
    const float* wg2  = (const float*)d_in[8];
    const float* bg2  = (const float*)d_in[9];
    const float* a1   = (const float*)d_in[10];
    const float* a2   = (const float*)d_in[11];
    const float* a3   = (const float*)d_in[12];
    const float* a4   = (const float*)d_in[13];
    float* out = (float*)d_out;

    float *bqkv, *bg1f, *qkvp, *qkvb, *g1;
    __nv_bfloat16 *Wqh, *Wql, *Wgh, *Wgl, *Xh, *Xl;
    cudaGetSymbolAddress((void**)&bqkv, g_bqkv);
    cudaGetSymbolAddress((void**)&bg1f, g_bg1);
    cudaGetSymbolAddress((void**)&qkvp, g_qkvp);
    cudaGetSymbolAddress((void**)&qkvb, g_qkv);
    cudaGetSymbolAddress((void**)&g1,   g_g1);
    cudaGetSymbolAddress((void**)&Wqh,  g_Wq_hi);
    cudaGetSymbolAddress((void**)&Wql,  g_Wq_lo);
    cudaGetSymbolAddress((void**)&Wgh,  g_Wg_hi);
    cudaGetSymbolAddress((void**)&Wgl,  g_Wg_lo);
    cudaGetSymbolAddress((void**)&Xh,   g_Xhi);
    cudaGetSymbolAddress((void**)&Xl,   g_Xlo);

    cudaFuncSetAttribute(mma_gemm, cudaFuncAttributeMaxDynamicSharedMemorySize, GEMM_SMEM);

    static cudaStream_t s1 = nullptr, s2 = nullptr;
    static cudaEvent_t evRoot, evSPLIT, evW, evBIAS, evGATE, evPIPE;
    static cudaEvent_t evC[4];
    if (s1 == nullptr) {
        cudaStreamCreateWithFlags(&s1, cudaStreamNonBlocking);
        cudaStreamCreateWithFlags(&s2, cudaStreamNonBlocking);
        cudaEventCreateWithFlags(&evRoot,  cudaEventDisableTiming);
        cudaEventCreateWithFlags(&evSPLIT, cudaEventDisableTiming);
        cudaEventCreateWithFlags(&evW,     cudaEventDisableTiming);
        cudaEventCreateWithFlags(&evBIAS,  cudaEventDisableTiming);
        cudaEventCreateWithFlags(&evGATE,  cudaEventDisableTiming);
        cudaEventCreateWithFlags(&evPIPE,  cudaEventDisableTiming);
        for (int i = 0; i < 4; i++)
            cudaEventCreateWithFlags(&evC[i], cudaEventDisableTiming);
    }

    dim3 blk(256);

    cudaEventRecord(evRoot, 0);
    cudaStreamWaitEvent(s1, evRoot, 0);
    cudaStreamWaitEvent(s2, evRoot, 0);

    // s0: x split
    split4_kernel<<<16384, blk>>>((const float4*)x, (uint2*)Xh, (uint2*)Xl, 4194304);
    cudaEventRecord(evSPLIT, 0);

    // s1: qkv weight fold
    sgemm_fold64<<<dim3(8, 24), blk, 0, s1>>>(wqkv, w0, Wqh, Wql, 512, 512);
    cudaEventRecord(evW, s1);

    // s2: gate weight fold + bias folds
    sgemm_fold64<<<dim3(8, 4), blk, 0, s2>>>(wg1, w0, Wgh, Wgl, 512, 512);
    fold_bias<<<224, blk, 0, s2>>>(wqkv, wg1, bg1, b0);
    cudaEventRecord(evBIAS, s2);

    // s0: qkv GEMM in 4 batch-pair chunks (128x128 CTAs, 2 CTAs/SM)
    cudaStreamWaitEvent(0, evW, 0);
    for (int p = 0; p < 4; p++) {
        mma_gemm<<<dim3(12, 32, 2), blk, GEMM_SMEM>>>(
            Wqh, Wql, Xh, Xl, qkvp, 1536, p * 2);
        cudaEventRecord(evC[p], 0);
    }

    // s1: pipelined dwconv + qk per batch pair
    cudaStreamWaitEvent(s1, evBIAS, 0);
    for (int p = 0; p < 4; p++) {
        cudaStreamWaitEvent(s1, evC[p], 0);
        dwconv_kernel<<<3072, blk, 0, s1>>>(qkvp, wdw, bqkv, qkvb, p * 3072);
        qk_gemm<<<dim3(8, 16), blk, 0, s1>>>(qkvb, p * 16);
    }
    inv_norm<<<32, blk, 0, s1>>>();
    cudaEventRecord(evPIPE, s1);

    // s2: gate GEMM (bf16x3) + gate pipeline
    cudaStreamWaitEvent(s2, evSPLIT, 0);
    mma_gemm<<<dim3(2, 32, 8), blk, GEMM_SMEM, s2>>>(
        Wgh, Wgl, Xh, Xl, g1, 256, 0);
    gate_dot<<<128, blk, 0, s2>>>(g1, wg2, bg1f, bg2);
    gate_fin<<<1, 32, 0, s2>>>();
    cudaEventRecord(evGATE, s2);

    // s0: join and fused attention output
    cudaStreamWaitEvent(0, evPIPE, 0);
    cudaStreamWaitEvent(0, evGATE, 0);
    attn_out<<<dim3(8, 64), blk>>>(qkvb, temp, a1, a2, a3, a4, out);
}